// round 17
// baseline (speedup 1.0000x reference)
#include <cuda_runtime.h>

// ChamferDistance2D via exact grid-accelerated NN search.
// B=8, N=M=8192, 2D fp32 points ~ N(0,1).
//
// Grid: G=256 cells over [-8,8]^2 (h=0.0625), per (batch, side) set -> 16 grids.
// Build: atomicAdd slot per point, cap CAP per cell; overflow + out-of-box points
//        go to a per-set overflow list that every query scans -> exactness never
//        depends on capacity. Counts re-zeroed every launch (graph-replay safe).
// Query: expanding Chebyshev rings; after finishing ring r, any unscanned point
//        is >= r*h away (cell-index gap k => distance >= (k-1)*h), so stop when
//        best <= (r*h)^2. Exact min; order-independent => deterministic.
// Sum:   per-query mins block-reduced in fixed order, finalized in fixed order,
//        scaled by 1/8192 (= sum_b mean(dist1)+mean(dist2)).

#define G      256
#define GCELLS (G * G)
#define CAP    24
#define OVCAP  512
#define NPTS   8192
#define NSETS  16                 // b*2 + side (side 0 = p1, 1 = p2)
#define BOXF   8.0f
#define HF     0.0625f            // 2*BOX/G
#define INVHF  16.0f              // G/(2*BOX)
#define QBLK   256
#define NQ     (NSETS * NPTS)     // 131072 queries (both directions, all batches)
#define QGRID  (NQ / QBLK)        // 512

__device__ unsigned g_cnt[NSETS][GCELLS];
__device__ float2   g_cellpts[NSETS][GCELLS * CAP];
__device__ unsigned g_ovf_cnt[NSETS];
__device__ float2   g_ovf[NSETS][OVCAP];
__device__ float    g_partial[QGRID];

__global__ void __launch_bounds__(256)
zero_k() {
    int i = blockIdx.x * blockDim.x + threadIdx.x;   // NSETS*GCELLS/4 uint4 stores
    ((uint4*)g_cnt)[i] = make_uint4(0u, 0u, 0u, 0u);
    if (i < NSETS) g_ovf_cnt[i] = 0u;
}

__global__ void __launch_bounds__(256)
build_k(const float2* __restrict__ p1, const float2* __restrict__ p2) {
    int i = blockIdx.x * blockDim.x + threadIdx.x;   // 0..NQ-1
    int s = i >> 13;                                  // set = b*2 + side
    int j = i & (NPTS - 1);
    const float2* src = (s & 1) ? p2 : p1;
    float2 p = src[(s >> 1) * NPTS + j];
    if (p.x > -BOXF && p.x < BOXF && p.y > -BOXF && p.y < BOXF) {
        int cx = (int)((p.x + BOXF) * INVHF);
        int cy = (int)((p.y + BOXF) * INVHF);
        int cell = cy * G + cx;
        unsigned slot = atomicAdd(&g_cnt[s][cell], 1u);
        if (slot < CAP) { g_cellpts[s][cell * CAP + slot] = p; return; }
    }
    unsigned o = atomicAdd(&g_ovf_cnt[s], 1u);
    if (o < OVCAP) g_ovf[s][o] = p;
}

__device__ __forceinline__ void scan_row(const unsigned* __restrict__ cnt,
                                         const float2* __restrict__ cp,
                                         int y, int x0, int x1,
                                         float qx, float qy, float& best) {
    for (int x = x0; x <= x1; x++) {
        int cell = y * G + x;
        unsigned c = min(cnt[cell], (unsigned)CAP);
        const float2* base = cp + cell * CAP;
        for (unsigned k = 0; k < c; k++) {
            float2 p = base[k];
            float dx = qx - p.x, dy = qy - p.y;
            best = fminf(best, fmaf(dx, dx, dy * dy));
        }
    }
}

__device__ __forceinline__ void scan_col(const unsigned* __restrict__ cnt,
                                         const float2* __restrict__ cp,
                                         int x, int y0, int y1,
                                         float qx, float qy, float& best) {
    for (int y = y0; y <= y1; y++) {
        int cell = y * G + x;
        unsigned c = min(cnt[cell], (unsigned)CAP);
        const float2* base = cp + cell * CAP;
        for (unsigned k = 0; k < c; k++) {
            float2 p = base[k];
            float dx = qx - p.x, dy = qy - p.y;
            best = fminf(best, fmaf(dx, dx, dy * dy));
        }
    }
}

__global__ void __launch_bounds__(QBLK)
query_k(const float2* __restrict__ p1, const float2* __restrict__ p2) {
    __shared__ float sm[QBLK];
    int qid = blockIdx.x * QBLK + threadIdx.x;
    int ss  = qid >> 13;              // query set
    int j   = qid & (NPTS - 1);
    int b   = ss >> 1;
    int dir = ss & 1;                 // 0: q=p1,t=p2   1: q=p2,t=p1
    const float2* qb = dir ? p2 : p1;
    float2 q = qb[b * NPTS + j];
    int ts = b * 2 + (dir ^ 1);       // target set
    const unsigned* cnt = g_cnt[ts];
    const float2*   cp  = g_cellpts[ts];

    float best = __int_as_float(0x7f800000);

    // Overflow / out-of-box points: always scanned -> exactness guaranteed.
    unsigned no = min(g_ovf_cnt[ts], (unsigned)OVCAP);
    for (unsigned k = 0; k < no; k++) {
        float2 p = g_ovf[ts][k];
        float dx = q.x - p.x, dy = q.y - p.y;
        best = fminf(best, fmaf(dx, dx, dy * dy));
    }

    int cx = min(max((int)((q.x + BOXF) * INVHF), 0), G - 1);
    int cy = min(max((int)((q.y + BOXF) * INVHF), 0), G - 1);

    for (int r = 0;; r++) {
        int x0 = max(cx - r, 0), x1 = min(cx + r, G - 1);
        int y0 = max(cy - r, 0), y1 = min(cy + r, G - 1);
        if (r == 0) {
            scan_row(cnt, cp, cy, cx, cx, q.x, q.y, best);
        } else {
            if (cy - r >= 0)     scan_row(cnt, cp, cy - r, x0, x1, q.x, q.y, best);
            if (cy + r <= G - 1) scan_row(cnt, cp, cy + r, x0, x1, q.x, q.y, best);
            int yy0 = max(cy - r + 1, 0), yy1 = min(cy + r - 1, G - 1);
            if (cx - r >= 0)     scan_col(cnt, cp, cx - r, yy0, yy1, q.x, q.y, best);
            if (cx + r <= G - 1) scan_col(cnt, cp, cx + r, yy0, yy1, q.x, q.y, best);
        }
        float dmin = r * HF;                       // ring r+1 is >= r*h away
        if (best <= dmin * dmin) break;
        if (x0 == 0 && y0 == 0 && x1 == G - 1 && y1 == G - 1) break;  // all scanned
    }

    sm[threadIdx.x] = best;
    __syncthreads();
#pragma unroll
    for (int w = QBLK / 2; w > 0; w >>= 1) {
        if (threadIdx.x < w) sm[threadIdx.x] += sm[threadIdx.x + w];
        __syncthreads();
    }
    if (threadIdx.x == 0) g_partial[blockIdx.x] = sm[0];
}

__global__ void __launch_bounds__(QGRID)
finalize_k(float* __restrict__ out) {
    __shared__ float sm[QGRID];
    int t = threadIdx.x;
    sm[t] = g_partial[t];
    __syncthreads();
#pragma unroll
    for (int w = QGRID / 2; w > 0; w >>= 1) {
        if (t < w) sm[t] += sm[t + w];
        __syncthreads();
    }
    if (t == 0) out[0] = sm[0] * (1.0f / 8192.0f);
}

extern "C" void kernel_launch(void* const* d_in, const int* in_sizes, int n_in,
                              void* d_out, int out_size) {
    const float2* p1 = (const float2*)d_in[0];
    const float2* p2 = (const float2*)d_in[1];
    float* out = (float*)d_out;

    zero_k<<<(NSETS * GCELLS / 4) / 256, 256>>>();
    build_k<<<NQ / 256, 256>>>(p1, p2);
    query_k<<<QGRID, QBLK>>>(p1, p2);
    finalize_k<<<1, QGRID>>>(out);
}